// round 5
// baseline (speedup 1.0000x reference)
#include <cuda_runtime.h>
#include <math.h>

#define FULL 0xffffffffu

static constexpr int B_    = 4;
static constexpr int N_    = 2000;
static constexpr int K_    = 5;
static constexpr int D_    = 32;
static constexpr int H1_   = 160;   // 32 * 5 heads
static constexpr int ROWS  = B_ * N_;           // 8000
static constexpr float MINN = 1e-15f;
static constexpr float MAXN = 1.0f - 4e-3f;     // (1-EPS)/sqrt(c), c=1

// ---------------- scratch (no allocation allowed) ----------------
__device__ float g_feats[ROWS * D_];            // tangent feats  (1 MB)
__device__ float g_nbr[ROWS * K_ * D_];         // gathered nbr_t (5 MB)
__device__ float g_hb1[H1_];
__device__ float g_hb2[D_];
__device__ float g_hb1n2;
__device__ float g_hb2n2;

// ---------------- helpers ----------------
__device__ __forceinline__ float wsum(float v) {
#pragma unroll
    for (int o = 16; o; o >>= 1) v += __shfl_xor_sync(FULL, v, o);
    return v;
}

__device__ __forceinline__ float artanh_(float x) {
    x = fminf(fmaxf(x, -1.0f + 1e-7f), 1.0f - 1e-7f);
    return 0.5f * (log1pf(x) - log1pf(-x));
}

// proj(expmap0(u)) for a 32-d tangent vector (lane = dim). Returns point value,
// sets np2 = squared norm of the resulting ball point.
__device__ __forceinline__ float ball_point(float u, float& np2) {
    float n2 = wsum(u * u);
    float n  = fmaxf(sqrtf(n2), MINN);
    float e  = tanhf(n) / n;
    float pv = e * u;
    float np = e * sqrtf(n2);
    float nn = fmaxf(np, MINN);
    if (nn > MAXN) { pv *= MAXN / nn; np = MAXN; }
    np2 = np * np;
    return pv;
}

// Full hnn_layer: proj(expmap0(relu(logmap0(proj(mobius_add(proj(mobius_matvec(W,x)), hb))))))
// x is 32-d in smem (sx), output has NI*32 dims (NI regs/lane, row = lane + 32*i).
// Wt is transposed weights in smem: Wt[d*NI*32 + row]. hb in smem, y2 = |hb|^2.
// All radial norms tracked analytically; only 2 extra warp reductions here.
template <int NI>
__device__ __forceinline__ void hnn_point(
    const float* Wt, const float* hb, float y2,
    const float* sx, float xn2, int lane,
    float o[NI], float& no_out)
{
    // mobius_matvec
    float mx[NI];
#pragma unroll
    for (int i = 0; i < NI; i++) mx[i] = 0.f;
#pragma unroll
    for (int d = 0; d < 32; d++) {
        float xd = sx[d];
#pragma unroll
        for (int i = 0; i < NI; i++) mx[i] += Wt[d * NI * 32 + lane + 32 * i] * xd;
    }
    float p = 0.f;
#pragma unroll
    for (int i = 0; i < NI; i++) p += mx[i] * mx[i];
    float mxn2 = wsum(p);
    float xn  = fmaxf(sqrtf(xn2), MINN);
    float mxn = fmaxf(sqrtf(mxn2), MINN);
    float r   = tanhf(mxn / xn * artanh_(xn));

    float res[NI]; float nres;
    if (mxn2 == 0.f) {
#pragma unroll
        for (int i = 0; i < NI; i++) res[i] = 0.f;
        nres = 0.f;
    } else {
        float s = r / mxn;
#pragma unroll
        for (int i = 0; i < NI; i++) res[i] = mx[i] * s;
        nres = r;
    }
    // proj
    {
        float n = fmaxf(nres, MINN);
        if (n > MAXN) {
            float s = MAXN / n;
#pragma unroll
            for (int i = 0; i < NI; i++) res[i] *= s;
            nres = MAXN;
        }
    }
    // mobius_add(res, hb) ; |num|^2 derived analytically from (x2, y2, xy)
    float x2 = nres * nres;
    p = 0.f;
#pragma unroll
    for (int i = 0; i < NI; i++) p += res[i] * hb[lane + 32 * i];
    float xy  = wsum(p);
    float A   = 1.f + 2.f * xy + y2;
    float Bc  = 1.f - x2;
    float den = fmaxf(1.f + 2.f * xy + x2 * y2, MINN);
    float m[NI];
#pragma unroll
    for (int i = 0; i < NI; i++) m[i] = (A * res[i] + Bc * hb[lane + 32 * i]) / den;
    float num2 = A * A * x2 + 2.f * A * Bc * xy + Bc * Bc * y2;
    float nm   = sqrtf(fmaxf(num2, 0.f)) / den;
    // proj
    {
        float n = fmaxf(nm, MINN);
        if (n > MAXN) {
            float s = MAXN / n;
#pragma unroll
            for (int i = 0; i < NI; i++) m[i] *= s;
            nm = MAXN;
        }
    }
    // relu(logmap0(.))
    float nl = fmaxf(nm, MINN);
    float la = artanh_(nl) / nl;
    float t[NI];
#pragma unroll
    for (int i = 0; i < NI; i++) t[i] = fmaxf(la * m[i], 0.f);
    p = 0.f;
#pragma unroll
    for (int i = 0; i < NI; i++) p += t[i] * t[i];
    float tn2 = wsum(p);
    // proj(expmap0(.))
    float tn = fmaxf(sqrtf(tn2), MINN);
    float ea = tanhf(tn) / tn;
    float no = ea * sqrtf(tn2);
#pragma unroll
    for (int i = 0; i < NI; i++) o[i] = ea * t[i];
    {
        float n = fmaxf(no, MINN);
        if (n > MAXN) {
            float s = MAXN / n;
#pragma unroll
            for (int i = 0; i < NI; i++) o[i] *= s;
            no = MAXN;
        }
    }
    no_out = no;
}

// ---------------- kernel 0: hb = proj(expmap0(bias)) ----------------
__global__ void k_hb(const float* __restrict__ b1, const float* __restrict__ b2) {
    int w = threadIdx.x >> 5, lane = threadIdx.x & 31;
    if (w == 0) {
        float bv[5]; float s = 0.f;
#pragma unroll
        for (int i = 0; i < 5; i++) { bv[i] = b1[lane + 32 * i]; s += bv[i] * bv[i]; }
        s = wsum(s);
        float n  = fmaxf(sqrtf(s), MINN);
        float e  = tanhf(n) / n;
        float nh = e * sqrtf(s);
        float sc = e;
        float nn = fmaxf(nh, MINN);
        if (nn > MAXN) { sc *= MAXN / nn; nh = MAXN; }
#pragma unroll
        for (int i = 0; i < 5; i++) g_hb1[lane + 32 * i] = sc * bv[i];
        if (lane == 0) g_hb1n2 = nh * nh;
    } else if (w == 1) {
        float bv = b2[lane];
        float s  = wsum(bv * bv);
        float n  = fmaxf(sqrtf(s), MINN);
        float e  = tanhf(n) / n;
        float nh = e * sqrtf(s);
        float sc = e;
        float nn = fmaxf(nh, MINN);
        if (nn > MAXN) { sc *= MAXN / nn; nh = MAXN; }
        g_hb2[lane] = sc * bv;
        if (lane == 0) g_hb2n2 = nh * nh;
    }
}

// ---------------- kernel A: feats = logmap0(in_feats) ----------------
__global__ void k_feats(const float* __restrict__ in_feats) {
    int row  = (int)((blockIdx.x * blockDim.x + threadIdx.x) >> 5);
    int lane = threadIdx.x & 31;
    if (row >= ROWS) return;
    float u  = in_feats[row * 32 + lane];
    float n2 = wsum(u * u);
    float n  = fmaxf(sqrtf(n2), MINN);
    g_feats[row * 32 + lane] = artanh_(n) / n * u;
}

// ---------------- kernel B: nbr_t = in_nei @ feats  (sparse gather) ----------
// One warp scans one 2000-float row of the (one-hot) adjacency; ballot finds
// the nonzeros; each nonzero adds w * feats[m] (lane = dim). Exact for any
// in_nei since zero terms contribute exactly 0.
__global__ void k_gather(const float* __restrict__ nei) {
    int row  = (int)((blockIdx.x * blockDim.x + threadIdx.x) >> 5);  // [0, 40000)
    int lane = threadIdx.x & 31;
    if (row >= ROWS * K_) return;
    int b = row / (N_ * K_);
    const float4* base = (const float4*)(nei + (size_t)row * N_);
    const float*  fb   = g_feats + b * N_ * 32;

    // phase 1: batch all loads (MLP ~ 16)
    float4 v[16];
#pragma unroll
    for (int j = 0; j < 16; j++) {
        int pos = j * 32 + lane;
        v[j] = make_float4(0.f, 0.f, 0.f, 0.f);
        if (pos < 500) v[j] = base[pos];
    }
    // phase 2: find + accumulate nonzeros
    float acc = 0.f;
#pragma unroll
    for (int j = 0; j < 16; j++) {
        bool nz = (v[j].x != 0.f) | (v[j].y != 0.f) | (v[j].z != 0.f) | (v[j].w != 0.f);
        unsigned m = __ballot_sync(FULL, nz);
        while (m) {
            int src = __ffs(m) - 1; m &= m - 1;
            float vx = __shfl_sync(FULL, v[j].x, src);
            float vy = __shfl_sync(FULL, v[j].y, src);
            float vz = __shfl_sync(FULL, v[j].z, src);
            float vw = __shfl_sync(FULL, v[j].w, src);
            int mb = (j * 32 + src) * 4;
            if (vx != 0.f) acc += vx * fb[(mb + 0) * 32 + lane];
            if (vy != 0.f) acc += vy * fb[(mb + 1) * 32 + lane];
            if (vz != 0.f) acc += vz * fb[(mb + 2) * 32 + lane];
            if (vw != 0.f) acc += vw * fb[(mb + 3) * 32 + lane];
        }
    }
    g_nbr[row * 32 + lane] = acc;
}

// ---------------- kernel C: fused attention + hyperbolic layers ----------------
__global__ __launch_bounds__(128) void k_main(
    const float* __restrict__ W1, const float* __restrict__ W2,
    float* __restrict__ out, float* __restrict__ att_out)
{
    __shared__ float sW1t[32 * 160];   // Wt[d*160 + r]  (conflict-free: stride%32==0, lane-contig)
    __shared__ float sW2t[32 * 32];    // Wt[d*32  + r]
    __shared__ float shb1[160];
    __shared__ float shb2[32];
    __shared__ float sx[4][32];
    __shared__ float skvq[4][6 * 160]; // slots 0..4 = kv_k, slot 5 = q (post-logmap0)
    __shared__ float satt[4][25];
    __shared__ float sy2[2];

    int t = threadIdx.x;
    for (int i = t; i < 160 * 32; i += 128) {
        int r = i >> 5, d = i & 31;
        sW1t[d * 160 + r] = W1[i];
    }
    for (int i = t; i < 32 * 32; i += 128) {
        int r = i >> 5, d = i & 31;
        sW2t[d * 32 + r] = W2[i];
    }
    for (int i = t; i < 160; i += 128) shb1[i] = g_hb1[i];
    if (t < 32) shb2[t] = g_hb2[t];
    if (t == 0) { sy2[0] = g_hb1n2; sy2[1] = g_hb2n2; }
    __syncthreads();

    int w = t >> 5, lane = t & 31;
    int row = blockIdx.x * 4 + w;          // grid = ROWS/4 exactly
    float* sxw = sx[w];
    float* skv = skvq[w];
    float y2_1 = sy2[0], y2_2 = sy2[1];

    // agent -> q
    {
        float u = g_feats[row * 32 + lane];
        float xn2;
        float pv = ball_point(u, xn2);
        __syncwarp(); sxw[lane] = pv; __syncwarp();
        float o[5], no;
        hnn_point<5>(sW1t, shb1, y2_1, sxw, xn2, lane, o, no);
        float n  = fmaxf(no, MINN);
        float ql = artanh_(n) / n;
#pragma unroll
        for (int i = 0; i < 5; i++) skv[5 * 160 + lane + 32 * i] = ql * o[i];
    }
    // neighbors -> kv (values == keys in the reference)
    for (int k = 0; k < K_; k++) {
        float u = g_nbr[(row * K_ + k) * 32 + lane];
        float xn2;
        float pv = ball_point(u, xn2);
        __syncwarp(); sxw[lane] = pv; __syncwarp();
        float o[5], no;
        hnn_point<5>(sW1t, shb1, y2_1, sxw, xn2, lane, o, no);
        float n  = fmaxf(no, MINN);
        float ql = artanh_(n) / n;
#pragma unroll
        for (int i = 0; i < 5; i++) skv[k * 160 + lane + 32 * i] = ql * o[i];
    }
    __syncwarp();

    // attention: head h fast axis -> element d*5+h
    if (lane < 25) {
        int h = lane / 5, kk = lane % 5;
        float lg = 0.f;
#pragma unroll
        for (int d = 0; d < 32; d++)
            lg += skv[5 * 160 + d * 5 + h] * skv[kk * 160 + d * 5 + h];
        satt[w][h * 5 + kk] = lg;
    }
    __syncwarp();
    if (lane < 5) {
        float v[5]; float mxv = -1e30f;
#pragma unroll
        for (int j = 0; j < 5; j++) { v[j] = satt[w][lane * 5 + j]; mxv = fmaxf(mxv, v[j]); }
        float s = 0.f;
#pragma unroll
        for (int j = 0; j < 5; j++) { v[j] = expf(v[j] - mxv); s += v[j]; }
        float inv = 1.f / s;
#pragma unroll
        for (int j = 0; j < 5; j++) {
            float a = v[j] * inv;
            satt[w][lane * 5 + j] = a;
            if (att_out) att_out[(row * 5 + lane) * 5 + j] = a;
        }
    }
    __syncwarp();

    // out[d] = mean_h sum_k att[h,k] * kv[k][d*5+h]
    float od = 0.f;
#pragma unroll
    for (int h = 0; h < 5; h++)
#pragma unroll
        for (int kk = 0; kk < 5; kk++)
            od += satt[w][h * 5 + kk] * skv[kk * 160 + lane * 5 + h];
    od *= (1.0f / 5.0f);

    // final: proj(expmap0(out)) -> hnn_layer(W2, b2)
    {
        float xn2;
        float pv = ball_point(od, xn2);
        __syncwarp(); sxw[lane] = pv; __syncwarp();
        float o[1], no;
        hnn_point<1>(sW2t, shb2, y2_2, sxw, xn2, lane, o, no);
        out[row * 32 + lane] = o[0];
    }
}

// ---------------- launch ----------------
extern "C" void kernel_launch(void* const* d_in, const int* in_sizes, int n_in,
                              void* d_out, int out_size) {
    const float* in_feats = (const float*)d_in[0];
    const float* in_nei   = (const float*)d_in[1];
    const float* W1       = (const float*)d_in[2];
    const float* b1       = (const float*)d_in[3];
    const float* W2       = (const float*)d_in[4];
    const float* b2       = (const float*)d_in[5];
    float* out = (float*)d_out;
    // out (B*N*32 = 256000) followed by att_record (B*N*5*5 = 200000), if present.
    float* att = (out_size >= ROWS * 32 + ROWS * 25) ? (out + ROWS * 32) : nullptr;

    k_hb<<<1, 64>>>(b1, b2);
    k_feats<<<(ROWS + 7) / 8, 256>>>(in_feats);            // 8 warps/block
    k_gather<<<(ROWS * K_ + 7) / 8, 256>>>(in_nei);        // 1 warp per (b,n,k)
    k_main<<<ROWS / 4, 128>>>(W1, W2, out, att);           // 1 warp per (b,n)
}

// round 6
// speedup vs baseline: 2.0882x; 2.0882x over previous
#include <cuda_runtime.h>
#include <math.h>

#define FULL 0xffffffffu

static constexpr int B_    = 4;
static constexpr int N_    = 2000;
static constexpr int K_    = 5;
static constexpr int H1_   = 160;   // 32 * 5 heads
static constexpr int ROWS  = B_ * N_;           // 8000
static constexpr float MINN = 1e-15f;
static constexpr float MAXN = 1.0f - 4e-3f;     // (1-EPS)/sqrt(c), c=1

static constexpr int HNN1_BLOCKS   = 250;                 // 8 warps x 4 rows = 32 rows/block
static constexpr int GATHER_BLOCKS = (ROWS * K_) / 8;     // 5000 (one warp per (b,n,k))

// ---------------- scratch (no allocation allowed) ----------------
__device__ int   g_nidx[ROWS * K_];     // neighbor index per (b,n,k)
__device__ float g_kv[ROWS * H1_];      // post-logmap0 hnn1 output per agent (5.1 MB)

// ---------------- helpers ----------------
__device__ __forceinline__ float wsum(float v) {
#pragma unroll
    for (int o = 16; o; o >>= 1) v += __shfl_xor_sync(FULL, v, o);
    return v;
}

__device__ __forceinline__ float artanh_(float x) {
    x = fminf(fmaxf(x, -1.0f + 1e-7f), 1.0f - 1e-7f);
    return 0.5f * (log1pf(x) - log1pf(-x));
}

// proj(expmap0(u)) for a 32-d tangent vector (lane = dim). Returns point value,
// sets np2 = squared norm of the resulting ball point.
__device__ __forceinline__ float ball_point(float u, float& np2) {
    float n2 = wsum(u * u);
    float n  = fmaxf(sqrtf(n2), MINN);
    float e  = tanhf(n) / n;
    float pv = e * u;
    float np = e * sqrtf(n2);
    float nn = fmaxf(np, MINN);
    if (nn > MAXN) { pv *= MAXN / nn; np = MAXN; }
    np2 = np * np;
    return pv;
}

// Full hnn_layer for J points at once (amortizes W smem reads J-fold).
// x[j] = ball-point value at dim=lane (broadcast via shfl), output NI*32 dims,
// row r = lane + 32*i. Wt transposed in smem: Wt[d*NI*32 + r]. hb in smem.
template <int J, int NI>
__device__ __forceinline__ void hnn_batch(
    const float* Wt, const float* hb, float y2,
    const float x[J], const float xn2a[J], int lane,
    float o[J][NI], float no_out[J])
{
    float mx[J][NI];
#pragma unroll
    for (int j = 0; j < J; j++)
#pragma unroll
        for (int i = 0; i < NI; i++) mx[j][i] = 0.f;

#pragma unroll
    for (int d = 0; d < 32; d++) {
        float wv[NI];
#pragma unroll
        for (int i = 0; i < NI; i++) wv[i] = Wt[d * NI * 32 + lane + 32 * i];
#pragma unroll
        for (int j = 0; j < J; j++) {
            float xd = __shfl_sync(FULL, x[j], d);
#pragma unroll
            for (int i = 0; i < NI; i++) mx[j][i] = fmaf(wv[i], xd, mx[j][i]);
        }
    }

#pragma unroll
    for (int j = 0; j < J; j++) {
        float p = 0.f;
#pragma unroll
        for (int i = 0; i < NI; i++) p += mx[j][i] * mx[j][i];
        float mxn2 = wsum(p);
        float xn  = fmaxf(sqrtf(xn2a[j]), MINN);
        float mxn = fmaxf(sqrtf(mxn2), MINN);
        float r   = tanhf(mxn / xn * artanh_(xn));

        float res[NI]; float nres;
        if (mxn2 == 0.f) {
#pragma unroll
            for (int i = 0; i < NI; i++) res[i] = 0.f;
            nres = 0.f;
        } else {
            float s = r / mxn;
#pragma unroll
            for (int i = 0; i < NI; i++) res[i] = mx[j][i] * s;
            nres = r;
        }
        {   // proj
            float n = fmaxf(nres, MINN);
            if (n > MAXN) {
                float s = MAXN / n;
#pragma unroll
                for (int i = 0; i < NI; i++) res[i] *= s;
                nres = MAXN;
            }
        }
        // mobius_add(res, hb) with analytic |num|^2
        float x2 = nres * nres;
        p = 0.f;
#pragma unroll
        for (int i = 0; i < NI; i++) p += res[i] * hb[lane + 32 * i];
        float xy  = wsum(p);
        float A   = 1.f + 2.f * xy + y2;
        float Bc  = 1.f - x2;
        float den = fmaxf(1.f + 2.f * xy + x2 * y2, MINN);
        float m[NI];
#pragma unroll
        for (int i = 0; i < NI; i++) m[i] = (A * res[i] + Bc * hb[lane + 32 * i]) / den;
        float num2 = A * A * x2 + 2.f * A * Bc * xy + Bc * Bc * y2;
        float nm   = sqrtf(fmaxf(num2, 0.f)) / den;
        {   // proj
            float n = fmaxf(nm, MINN);
            if (n > MAXN) {
                float s = MAXN / n;
#pragma unroll
                for (int i = 0; i < NI; i++) m[i] *= s;
                nm = MAXN;
            }
        }
        // relu(logmap0(.))
        float nl = fmaxf(nm, MINN);
        float la = artanh_(nl) / nl;
        float t[NI];
#pragma unroll
        for (int i = 0; i < NI; i++) t[i] = fmaxf(la * m[i], 0.f);
        p = 0.f;
#pragma unroll
        for (int i = 0; i < NI; i++) p += t[i] * t[i];
        float tn2 = wsum(p);
        // proj(expmap0(.))
        float tn = fmaxf(sqrtf(tn2), MINN);
        float ea = tanhf(tn) / tn;
        float no = ea * sqrtf(tn2);
#pragma unroll
        for (int i = 0; i < NI; i++) o[j][i] = ea * t[i];
        {
            float n = fmaxf(no, MINN);
            if (n > MAXN) {
                float s = MAXN / n;
#pragma unroll
                for (int i = 0; i < NI; i++) o[j][i] *= s;
                no = MAXN;
            }
        }
        no_out[j] = no;
    }
}

// ---------------- kernel 1: fused { hnn1 per agent  |  one-hot index extract } ---
// Blocks [0, HNN1_BLOCKS): hnn1 (scheduled first so they hide under the DRAM scan).
// Blocks [HNN1_BLOCKS, +GATHER_BLOCKS): one warp scans one 2000-float one-hot
// row of in_nei with early exit (expected ~56% of bytes read) and records the
// index of the (exact 1.0f) nonzero. kv for neighbor m == agent-hnn1 of row m.
__global__ __launch_bounds__(256) void k_scan(
    const float* __restrict__ in_feats, const float* __restrict__ nei,
    const float* __restrict__ W1, const float* __restrict__ b1)
{
    __shared__ float sW1t[32 * 160];
    __shared__ float shb1[160];
    __shared__ float sy2;

    int t = threadIdx.x, w = t >> 5, lane = t & 31;

    if (blockIdx.x >= HNN1_BLOCKS) {
        // ---- index extraction ----
        int rownk = (int)(blockIdx.x - HNN1_BLOCKS) * 8 + w;   // [0, 40000)
        const float4* base = (const float4*)(nei + (size_t)rownk * N_);
        int idx = 0;
#pragma unroll 1
        for (int j0 = 0; j0 < 16; j0 += 2) {
            int p0 = j0 * 32 + lane, p1 = p0 + 32;
            float4 v0 = make_float4(0.f, 0.f, 0.f, 0.f);
            float4 v1 = make_float4(0.f, 0.f, 0.f, 0.f);
            if (p0 < 500) v0 = base[p0];
            if (p1 < 500) v1 = base[p1];
            int c0 = (v0.x != 0.f) ? 0 : (v0.y != 0.f) ? 1 : (v0.z != 0.f) ? 2 : (v0.w != 0.f) ? 3 : -1;
            int c1 = (v1.x != 0.f) ? 0 : (v1.y != 0.f) ? 1 : (v1.z != 0.f) ? 2 : (v1.w != 0.f) ? 3 : -1;
            unsigned m0 = __ballot_sync(FULL, c0 >= 0);
            unsigned m1 = __ballot_sync(FULL, c1 >= 0);
            if (m0 | m1) {
                if (m0) { int s = __ffs(m0) - 1; idx = (j0 * 32 + s) * 4 + __shfl_sync(FULL, c0, s); }
                else    { int s = __ffs(m1) - 1; idx = ((j0 + 1) * 32 + s) * 4 + __shfl_sync(FULL, c1, s); }
                break;
            }
        }
        if (lane == 0) g_nidx[rownk] = idx;
        return;
    }

    // ---- hnn1 per agent, 4 rows per warp ----
    for (int i = t; i < 160 * 32; i += 256) {
        int r = i >> 5, d = i & 31;
        sW1t[d * 160 + r] = W1[i];
    }
    if (w == 0) {  // hb1 = proj(expmap0(b1))
        float bv[5]; float s = 0.f;
#pragma unroll
        for (int i = 0; i < 5; i++) { bv[i] = b1[lane + 32 * i]; s += bv[i] * bv[i]; }
        s = wsum(s);
        float n  = fmaxf(sqrtf(s), MINN);
        float e  = tanhf(n) / n;
        float nh = e * sqrtf(s);
        float sc = e;
        float nn = fmaxf(nh, MINN);
        if (nn > MAXN) { sc *= MAXN / nn; nh = MAXN; }
#pragma unroll
        for (int i = 0; i < 5; i++) shb1[lane + 32 * i] = sc * bv[i];
        if (lane == 0) sy2 = nh * nh;
    }
    __syncthreads();
    float y2 = sy2;

    int row0 = ((int)blockIdx.x * 8 + w) * 4;    // 4 consecutive rows
    float x[4], xn2[4];
#pragma unroll
    for (int j = 0; j < 4; j++) {
        float u  = in_feats[(size_t)(row0 + j) * 32 + lane];
        float n2 = wsum(u * u);
        float n  = fmaxf(sqrtf(n2), MINN);
        float f  = artanh_(n) / n * u;           // logmap0
        x[j] = ball_point(f, xn2[j]);            // proj(expmap0(.))
    }
    float o[4][5], no[4];
    hnn_batch<4, 5>(sW1t, shb1, y2, x, xn2, lane, o, no);
#pragma unroll
    for (int j = 0; j < 4; j++) {
        float n  = fmaxf(no[j], MINN);
        float ql = artanh_(n) / n;               // final logmap0 scale
#pragma unroll
        for (int i = 0; i < 5; i++)
            g_kv[(size_t)(row0 + j) * 160 + lane + 32 * i] = ql * o[j][i];
    }
}

// ---------------- kernel 2: attention + final hnn layer -------------------------
// One warp per (b,n). q and the 5 kv vectors come from g_kv (L2-resident).
// Element r = lane + 32*i has head (lane+2i)%5; each lane holds exactly one
// element per head, so logits reduce with predicated selects + 25 warp sums.
__global__ __launch_bounds__(256) void k_att(
    const float* __restrict__ W2, const float* __restrict__ b2,
    float* __restrict__ out, float* __restrict__ att_out)
{
    __shared__ float sW2t[32 * 32];
    __shared__ float shb2[32];
    __shared__ float sy2;
    __shared__ float strans[8][160];

    int t = threadIdx.x, w = t >> 5, lane = t & 31;
    for (int i = t; i < 32 * 32; i += 256) {
        int r = i >> 5, d = i & 31;
        sW2t[d * 32 + r] = W2[i];
    }
    if (w == 0) {  // hb2 = proj(expmap0(b2))
        float bv = b2[lane];
        float s  = wsum(bv * bv);
        float n  = fmaxf(sqrtf(s), MINN);
        float e  = tanhf(n) / n;
        float nh = e * sqrtf(s);
        float sc = e;
        float nn = fmaxf(nh, MINN);
        if (nn > MAXN) { sc *= MAXN / nn; nh = MAXN; }
        shb2[lane] = sc * bv;
        if (lane == 0) sy2 = nh * nh;
    }
    __syncthreads();
    float y2 = sy2;

    int row = (int)blockIdx.x * 8 + w;           // grid = ROWS/8 exactly
    int b   = row / N_;

    float q[5];
#pragma unroll
    for (int i = 0; i < 5; i++) q[i] = g_kv[(size_t)row * 160 + lane + 32 * i];

    int nv = (lane < 5) ? g_nidx[row * 5 + lane] : 0;
    float kvr[5][5];
#pragma unroll
    for (int k = 0; k < 5; k++) {
        int m = __shfl_sync(FULL, nv, k);
        const float* p = g_kv + (size_t)(b * N_ + m) * 160;
#pragma unroll
        for (int i = 0; i < 5; i++) kvr[k][i] = p[lane + 32 * i];
    }

    int hsel[5];
#pragma unroll
    for (int i = 0; i < 5; i++) hsel[i] = (lane + 2 * i) % 5;

    // logits[h][k] = sum over elements with head h of q*kv
    float lg[25];
#pragma unroll
    for (int k = 0; k < 5; k++) {
        float pr[5];
#pragma unroll
        for (int i = 0; i < 5; i++) pr[i] = q[i] * kvr[k][i];
#pragma unroll
        for (int h = 0; h < 5; h++) {
            float s = 0.f;
#pragma unroll
            for (int i = 0; i < 5; i++) s += (hsel[i] == h) ? pr[i] : 0.f;
            lg[h * 5 + k] = s;
        }
    }
#pragma unroll
    for (int e = 0; e < 25; e++) lg[e] = wsum(lg[e]);

    // softmax over k per head (warp-uniform in registers)
    float att[25];
#pragma unroll
    for (int h = 0; h < 5; h++) {
        float mxv = lg[h * 5];
#pragma unroll
        for (int k = 1; k < 5; k++) mxv = fmaxf(mxv, lg[h * 5 + k]);
        float s = 0.f;
#pragma unroll
        for (int k = 0; k < 5; k++) { float ev = expf(lg[h * 5 + k] - mxv); att[h * 5 + k] = ev; s += ev; }
        float inv = 1.f / s;
#pragma unroll
        for (int k = 0; k < 5; k++) att[h * 5 + k] *= inv;
    }

    if (att_out) {  // att_record[row, h, k] ; lane <-> h*5+k
        float val = 0.f;
#pragma unroll
        for (int e = 0; e < 25; e++) val = (lane == e) ? att[e] : val;
        if (lane < 25) att_out[(size_t)row * 25 + lane] = val;
    }

    // attended value per element, pre-scaled by 1/heads
    float ov[5];
#pragma unroll
    for (int i = 0; i < 5; i++) {
        float s = 0.f;
#pragma unroll
        for (int k = 0; k < 5; k++) {
            float a = 0.f;
#pragma unroll
            for (int h = 0; h < 5; h++) a = (hsel[i] == h) ? att[h * 5 + k] : a;
            s = fmaf(a, kvr[k][i], s);
        }
        ov[i] = s * 0.2f;
    }
    // transpose element space -> dim space: out[d] = sum_h ov[d*5+h]
#pragma unroll
    for (int i = 0; i < 5; i++) strans[w][lane + 32 * i] = ov[i];
    __syncwarp();
    float od = 0.f;
#pragma unroll
    for (int h = 0; h < 5; h++) od += strans[w][lane * 5 + h];

    // proj(expmap0(out)) -> hnn_layer(W2, b2)
    float xr[1], xn2[1];
    xr[0] = ball_point(od, xn2[0]);
    float o[1][1], no[1];
    hnn_batch<1, 1>(sW2t, shb2, y2, xr, xn2, lane, o, no);
    out[(size_t)row * 32 + lane] = o[0][0];
}

// ---------------- launch ----------------
extern "C" void kernel_launch(void* const* d_in, const int* in_sizes, int n_in,
                              void* d_out, int out_size) {
    const float* in_feats = (const float*)d_in[0];
    const float* in_nei   = (const float*)d_in[1];
    const float* W1       = (const float*)d_in[2];
    const float* b1       = (const float*)d_in[3];
    const float* W2       = (const float*)d_in[4];
    const float* b2       = (const float*)d_in[5];
    float* out = (float*)d_out;
    // out (B*N*32 = 256000) followed by att_record (B*N*5*5 = 200000), if present.
    float* att = (out_size >= ROWS * 32 + ROWS * 25) ? (out + ROWS * 32) : nullptr;

    k_scan<<<HNN1_BLOCKS + GATHER_BLOCKS, 256>>>(in_feats, in_nei, W1, b1);
    k_att<<<ROWS / 8, 256>>>(W2, b2, out, att);
}

// round 7
// speedup vs baseline: 2.3697x; 1.1348x over previous
#include <cuda_runtime.h>
#include <math.h>

#define FULL 0xffffffffu

static constexpr int B_    = 4;
static constexpr int N_    = 2000;
static constexpr int K_    = 5;
static constexpr int H1_   = 160;   // 32 * 5 heads
static constexpr int ROWS  = B_ * N_;           // 8000
static constexpr float MINN = 1e-15f;
static constexpr float MAXN = 1.0f - 4e-3f;     // (1-EPS)/sqrt(c), c=1

static constexpr int HNN1_BLOCKS   = 250;       // 8 warps x 4 rows = 32 rows/block
static constexpr int GATHER_BLOCKS = ROWS / 8;  // 1000: one warp per (b,n), 5 rows each

// ---------------- scratch (no allocation allowed) ----------------
__device__ int   g_nidx[ROWS * K_];     // neighbor index per (b,n,k)
__device__ float g_kv[ROWS * H1_];      // hnn1 output, HEAD-MAJOR: [row][h*32+d]

// ---------------- helpers ----------------
__device__ __forceinline__ float wsum(float v) {
#pragma unroll
    for (int o = 16; o; o >>= 1) v += __shfl_xor_sync(FULL, v, o);
    return v;
}

__device__ __forceinline__ float artanh_(float x) {
    x = fminf(fmaxf(x, -1.0f + 1e-7f), 1.0f - 1e-7f);
    return 0.5f * (log1pf(x) - log1pf(-x));
}

// proj(expmap0(u)) for a 32-d tangent vector (lane = dim).
__device__ __forceinline__ float ball_point(float u, float& np2) {
    float n2 = wsum(u * u);
    float n  = fmaxf(sqrtf(n2), MINN);
    float e  = tanhf(n) / n;
    float pv = e * u;
    float np = e * sqrtf(n2);
    float nn = fmaxf(np, MINN);
    if (nn > MAXN) { pv *= MAXN / nn; np = MAXN; }
    np2 = np * np;
    return pv;
}

// Full hnn_layer for J points (amortizes W smem reads J-fold).
// x[j] broadcast via shfl; output row r = lane + 32*i; Wt[d*NI*32 + r] in smem.
template <int J, int NI>
__device__ __forceinline__ void hnn_batch(
    const float* Wt, const float* hb, float y2,
    const float x[J], const float xn2a[J], int lane,
    float o[J][NI], float no_out[J])
{
    float mx[J][NI];
#pragma unroll
    for (int j = 0; j < J; j++)
#pragma unroll
        for (int i = 0; i < NI; i++) mx[j][i] = 0.f;

#pragma unroll
    for (int d = 0; d < 32; d++) {
        float wv[NI];
#pragma unroll
        for (int i = 0; i < NI; i++) wv[i] = Wt[d * NI * 32 + lane + 32 * i];
#pragma unroll
        for (int j = 0; j < J; j++) {
            float xd = __shfl_sync(FULL, x[j], d);
#pragma unroll
            for (int i = 0; i < NI; i++) mx[j][i] = fmaf(wv[i], xd, mx[j][i]);
        }
    }

#pragma unroll
    for (int j = 0; j < J; j++) {
        float p = 0.f;
#pragma unroll
        for (int i = 0; i < NI; i++) p += mx[j][i] * mx[j][i];
        float mxn2 = wsum(p);
        float xn  = fmaxf(sqrtf(xn2a[j]), MINN);
        float mxn = fmaxf(sqrtf(mxn2), MINN);
        float r   = tanhf(mxn / xn * artanh_(xn));

        float res[NI]; float nres;
        if (mxn2 == 0.f) {
#pragma unroll
            for (int i = 0; i < NI; i++) res[i] = 0.f;
            nres = 0.f;
        } else {
            float s = r / mxn;
#pragma unroll
            for (int i = 0; i < NI; i++) res[i] = mx[j][i] * s;
            nres = r;
        }
        {   // proj
            float n = fmaxf(nres, MINN);
            if (n > MAXN) {
                float s = MAXN / n;
#pragma unroll
                for (int i = 0; i < NI; i++) res[i] *= s;
                nres = MAXN;
            }
        }
        // mobius_add(res, hb) with analytic |num|^2
        float x2 = nres * nres;
        p = 0.f;
#pragma unroll
        for (int i = 0; i < NI; i++) p += res[i] * hb[lane + 32 * i];
        float xy  = wsum(p);
        float A   = 1.f + 2.f * xy + y2;
        float Bc  = 1.f - x2;
        float den = fmaxf(1.f + 2.f * xy + x2 * y2, MINN);
        float m[NI];
#pragma unroll
        for (int i = 0; i < NI; i++) m[i] = (A * res[i] + Bc * hb[lane + 32 * i]) / den;
        float num2 = A * A * x2 + 2.f * A * Bc * xy + Bc * Bc * y2;
        float nm   = sqrtf(fmaxf(num2, 0.f)) / den;
        {   // proj
            float n = fmaxf(nm, MINN);
            if (n > MAXN) {
                float s = MAXN / n;
#pragma unroll
                for (int i = 0; i < NI; i++) m[i] *= s;
                nm = MAXN;
            }
        }
        // relu(logmap0(.))
        float nl = fmaxf(nm, MINN);
        float la = artanh_(nl) / nl;
        float t[NI];
#pragma unroll
        for (int i = 0; i < NI; i++) t[i] = fmaxf(la * m[i], 0.f);
        p = 0.f;
#pragma unroll
        for (int i = 0; i < NI; i++) p += t[i] * t[i];
        float tn2 = wsum(p);
        // proj(expmap0(.))
        float tn = fmaxf(sqrtf(tn2), MINN);
        float ea = tanhf(tn) / tn;
        float no = ea * sqrtf(tn2);
#pragma unroll
        for (int i = 0; i < NI; i++) o[j][i] = ea * t[i];
        {
            float n = fmaxf(no, MINN);
            if (n > MAXN) {
                float s = MAXN / n;
#pragma unroll
                for (int i = 0; i < NI; i++) o[j][i] *= s;
                no = MAXN;
            }
        }
        no_out[j] = no;
    }
}

// ---------------- kernel 1: fused { hnn1 per agent | one-hot index extract } ----
// Blocks [0, HNN1_BLOCKS): hnn1 (J=2 twice, 4 rows/warp) -> g_kv head-major.
// Blocks after: one warp scans the 5 contiguous one-hot rows of one (b,n)
// concurrently (MLP=5), early-exiting each row when its 1.0 is found.
__global__ __launch_bounds__(256) void k_scan(
    const float* __restrict__ in_feats, const float* __restrict__ nei,
    const float* __restrict__ W1, const float* __restrict__ b1)
{
    __shared__ float sW1t[32 * 160];
    __shared__ float shb1[160];
    __shared__ float sy2;

    int t = threadIdx.x, w = t >> 5, lane = t & 31;

    if (blockIdx.x >= HNN1_BLOCKS) {
        // ---- 5-row concurrent one-hot scan ----
        int bn = ((int)blockIdx.x - HNN1_BLOCKS) * 8 + w;      // [0, 8000)
        const float* rowbase = nei + (size_t)bn * (K_ * N_);
        unsigned found = 0;
        int idx[5] = {0, 0, 0, 0, 0};
#pragma unroll 1
        for (int j = 0; j < 16; j++) {
            int pos = j * 32 + lane;
            bool inb = pos < 500;                               // 2000 floats = 500 float4
            float4 v[5];
#pragma unroll
            for (int k = 0; k < 5; k++) {
                v[k] = make_float4(0.f, 0.f, 0.f, 0.f);
                if (inb && !((found >> k) & 1))
                    v[k] = ((const float4*)(rowbase + k * N_))[pos];
            }
#pragma unroll
            for (int k = 0; k < 5; k++) {
                if ((found >> k) & 1) continue;                 // warp-uniform
                int c = (v[k].x != 0.f) ? 0 : (v[k].y != 0.f) ? 1
                      : (v[k].z != 0.f) ? 2 : (v[k].w != 0.f) ? 3 : -1;
                unsigned m = __ballot_sync(FULL, c >= 0);
                if (m) {
                    int s = __ffs(m) - 1;
                    idx[k] = (j * 32 + s) * 4 + __shfl_sync(FULL, c, s);
                    found |= 1u << k;
                }
            }
            if (found == 31u) break;
        }
        int myidx = 0;
#pragma unroll
        for (int k = 0; k < 5; k++) myidx = (lane == k) ? idx[k] : myidx;
        if (lane < 5) g_nidx[bn * 5 + lane] = myidx;
        return;
    }

    // ---- hnn1 per agent ----
    for (int i = t; i < 160 * 32; i += 256) {
        int r = i >> 5, d = i & 31;
        sW1t[d * 160 + r] = W1[i];
    }
    if (w == 0) {  // hb1 = proj(expmap0(b1))
        float bv[5]; float s = 0.f;
#pragma unroll
        for (int i = 0; i < 5; i++) { bv[i] = b1[lane + 32 * i]; s += bv[i] * bv[i]; }
        s = wsum(s);
        float n  = fmaxf(sqrtf(s), MINN);
        float e  = tanhf(n) / n;
        float nh = e * sqrtf(s);
        float sc = e;
        float nn = fmaxf(nh, MINN);
        if (nn > MAXN) { sc *= MAXN / nn; nh = MAXN; }
#pragma unroll
        for (int i = 0; i < 5; i++) shb1[lane + 32 * i] = sc * bv[i];
        if (lane == 0) sy2 = nh * nh;
    }
    __syncthreads();
    float y2 = sy2;

    int row00 = ((int)blockIdx.x * 8 + w) * 4;     // 4 rows per warp, J=2 twice
#pragma unroll 1
    for (int jj = 0; jj < 2; jj++) {
        int row0 = row00 + jj * 2;
        float x[2], xn2[2];
#pragma unroll
        for (int j = 0; j < 2; j++) {
            float u  = in_feats[(size_t)(row0 + j) * 32 + lane];
            float n2 = wsum(u * u);
            float n  = fmaxf(sqrtf(n2), MINN);
            float f  = artanh_(n) / n * u;         // logmap0
            x[j] = ball_point(f, xn2[j]);          // proj(expmap0(.))
        }
        float o[2][5], no[2];
        hnn_batch<2, 5>(sW1t, shb1, y2, x, xn2, lane, o, no);
#pragma unroll
        for (int j = 0; j < 2; j++) {
            float n  = fmaxf(no[j], MINN);
            float ql = artanh_(n) / n;             // final logmap0 scale
#pragma unroll
            for (int i = 0; i < 5; i++) {
                int r = lane + 32 * i;             // element r = d*5+h
                int pos = (r % 5) * 32 + (r / 5);  // head-major: h*32+d
                g_kv[(size_t)(row0 + j) * 160 + pos] = ql * o[j][i];
            }
        }
    }
}

// ---------------- kernel 2: attention + final hnn layer -------------------------
// One warp per (b,n). Head-major g_kv: register i == head i at dim=lane.
// No hsel predication, no smem transpose, softmax in place -> no spills.
__global__ __launch_bounds__(128) void k_att(
    const float* __restrict__ W2, const float* __restrict__ b2,
    float* __restrict__ out, float* __restrict__ att_out)
{
    __shared__ float sW2t[32 * 32];
    __shared__ float shb2[32];
    __shared__ float sy2;

    int t = threadIdx.x, w = t >> 5, lane = t & 31;
    for (int i = t; i < 32 * 32; i += 128) {
        int r = i >> 5, d = i & 31;
        sW2t[d * 32 + r] = W2[i];
    }
    if (w == 0) {  // hb2 = proj(expmap0(b2))
        float bv = b2[lane];
        float s  = wsum(bv * bv);
        float n  = fmaxf(sqrtf(s), MINN);
        float e  = tanhf(n) / n;
        float nh = e * sqrtf(s);
        float sc = e;
        float nn = fmaxf(nh, MINN);
        if (nn > MAXN) { sc *= MAXN / nn; nh = MAXN; }
        shb2[lane] = sc * bv;
        if (lane == 0) sy2 = nh * nh;
    }
    __syncthreads();
    float y2 = sy2;

    int row = (int)blockIdx.x * 4 + w;             // grid = ROWS/4 exactly
    int b   = row / N_;

    float q[5];
#pragma unroll
    for (int i = 0; i < 5; i++) q[i] = g_kv[(size_t)row * 160 + i * 32 + lane];

    int nv = (lane < 5) ? g_nidx[row * 5 + lane] : 0;
    float kvr[5][5];
#pragma unroll
    for (int k = 0; k < 5; k++) {
        int m = __shfl_sync(FULL, nv, k);
        const float* p = g_kv + (size_t)(b * N_ + m) * 160;
#pragma unroll
        for (int i = 0; i < 5; i++) kvr[k][i] = p[i * 32 + lane];
    }

    // logits[h][k] = sum_d q[h,d]*kv[k][h,d]  (d = lanes)
    float lg[25];
#pragma unroll
    for (int h = 0; h < 5; h++)
#pragma unroll
        for (int k = 0; k < 5; k++)
            lg[h * 5 + k] = wsum(q[h] * kvr[k][h]);

    // softmax over k per head, in place (warp-uniform)
#pragma unroll
    for (int h = 0; h < 5; h++) {
        float mxv = lg[h * 5];
#pragma unroll
        for (int k = 1; k < 5; k++) mxv = fmaxf(mxv, lg[h * 5 + k]);
        float s = 0.f;
#pragma unroll
        for (int k = 0; k < 5; k++) { float ev = __expf(lg[h * 5 + k] - mxv); lg[h * 5 + k] = ev; s += ev; }
        float inv = 1.f / s;
#pragma unroll
        for (int k = 0; k < 5; k++) lg[h * 5 + k] *= inv;
    }

    if (att_out) {  // att_record[row, h, k]; lane <-> h*5+k
        float val = 0.f;
#pragma unroll
        for (int e = 0; e < 25; e++) val = (lane == e) ? lg[e] : val;
        if (lane < 25) att_out[(size_t)row * 25 + lane] = val;
    }

    // out[d=lane] = (1/5) * sum_h sum_k att[h,k]*kv[k][h,lane]
    float od = 0.f;
#pragma unroll
    for (int h = 0; h < 5; h++) {
        float s = 0.f;
#pragma unroll
        for (int k = 0; k < 5; k++) s = fmaf(lg[h * 5 + k], kvr[k][h], s);
        od += s;
    }
    od *= 0.2f;

    // proj(expmap0(out)) -> hnn_layer(W2, b2)
    float xr[1], xn2[1];
    xr[0] = ball_point(od, xn2[0]);
    float o[1][1], no[1];
    hnn_batch<1, 1>(sW2t, shb2, y2, xr, xn2, lane, o, no);
    out[(size_t)row * 32 + lane] = o[0][0];
}

// ---------------- launch ----------------
extern "C" void kernel_launch(void* const* d_in, const int* in_sizes, int n_in,
                              void* d_out, int out_size) {
    const float* in_feats = (const float*)d_in[0];
    const float* in_nei   = (const float*)d_in[1];
    const float* W1       = (const float*)d_in[2];
    const float* b1       = (const float*)d_in[3];
    const float* W2       = (const float*)d_in[4];
    const float* b2       = (const float*)d_in[5];
    float* out = (float*)d_out;
    // out (B*N*32 = 256000) followed by att_record (B*N*5*5 = 200000), if present.
    float* att = (out_size >= ROWS * 32 + ROWS * 25) ? (out + ROWS * 32) : nullptr;

    k_scan<<<HNN1_BLOCKS + GATHER_BLOCKS, 256>>>(in_feats, in_nei, W1, b1);
    k_att<<<ROWS / 4, 128>>>(W2, b2, out, att);
}

// round 9
// speedup vs baseline: 2.4443x; 1.0315x over previous
#include <cuda_runtime.h>
#include <math.h>

#define FULL 0xffffffffu

static constexpr int B_    = 4;
static constexpr int N_    = 2000;
static constexpr int K_    = 5;
static constexpr int ROWS  = B_ * N_;           // 8000
static constexpr float MINN = 1e-15f;
static constexpr float MAXN = 1.0f - 4e-3f;     // (1-EPS)/sqrt(c), c=1

static constexpr int HNN1_BLOCKS   = 250;       // 8 warps x 4 rows = 32 rows/block
static constexpr int GATHER_BLOCKS = ROWS / 8;  // 1000: one warp per (b,n), 5 rows each
static constexpr int KV_STRIDE     = 256;       // padded: [row][d*8 + h]

// ---------------- scratch (no allocation allowed) ----------------
__device__ int   g_nidx[ROWS * K_];             // neighbor index per (b,n,k)
__device__ float g_kv[ROWS * KV_STRIDE];        // hnn1 output, dim-major padded (8.2 MB)

// ---------------- helpers ----------------
__device__ __forceinline__ float wsum(float v) {
#pragma unroll
    for (int o = 16; o; o >>= 1) v += __shfl_xor_sync(FULL, v, o);
    return v;
}

// artanh via single fast log: 0.5*log((1+x)/(1-x)). Rel err ~1e-6 (vs 1e-3 budget).
__device__ __forceinline__ float artanh_(float x) {
    x = fminf(fmaxf(x, -1.0f + 1e-7f), 1.0f - 1e-7f);
    return 0.5f * __logf(__fdividef(1.0f + x, 1.0f - x));
}

// proj(expmap0(u)) for a 32-d tangent vector (lane = dim).
__device__ __forceinline__ float ball_point(float u, float& np2) {
    float n2 = wsum(u * u);
    float n  = fmaxf(sqrtf(n2), MINN);
    float e  = __fdividef(tanhf(n), n);
    float pv = e * u;
    float np = e * sqrtf(n2);
    float nn = fmaxf(np, MINN);
    if (nn > MAXN) { pv *= __fdividef(MAXN, nn); np = MAXN; }
    np2 = np * np;
    return pv;
}

// Full hnn_layer for J points (amortizes W smem reads J-fold).
// x[j] broadcast via shfl; output row r = lane + 32*i; Wt[d*NI*32 + r] in smem.
template <int J, int NI>
__device__ __forceinline__ void hnn_batch(
    const float* Wt, const float* hb, float y2,
    const float x[J], const float xn2a[J], int lane,
    float o[J][NI], float no_out[J])
{
    float mx[J][NI];
#pragma unroll
    for (int j = 0; j < J; j++)
#pragma unroll
        for (int i = 0; i < NI; i++) mx[j][i] = 0.f;

#pragma unroll
    for (int d = 0; d < 32; d++) {
        float wv[NI];
#pragma unroll
        for (int i = 0; i < NI; i++) wv[i] = Wt[d * NI * 32 + lane + 32 * i];
#pragma unroll
        for (int j = 0; j < J; j++) {
            float xd = __shfl_sync(FULL, x[j], d);
#pragma unroll
            for (int i = 0; i < NI; i++) mx[j][i] = fmaf(wv[i], xd, mx[j][i]);
        }
    }

#pragma unroll
    for (int j = 0; j < J; j++) {
        float p = 0.f;
#pragma unroll
        for (int i = 0; i < NI; i++) p += mx[j][i] * mx[j][i];
        float mxn2 = wsum(p);
        float xn  = fmaxf(sqrtf(xn2a[j]), MINN);
        float mxn = fmaxf(sqrtf(mxn2), MINN);
        float r   = tanhf(__fdividef(mxn, xn) * artanh_(xn));

        float res[NI]; float nres;
        if (mxn2 == 0.f) {
#pragma unroll
            for (int i = 0; i < NI; i++) res[i] = 0.f;
            nres = 0.f;
        } else {
            float s = __fdividef(r, mxn);
#pragma unroll
            for (int i = 0; i < NI; i++) res[i] = mx[j][i] * s;
            nres = r;
        }
        {   // proj
            float n = fmaxf(nres, MINN);
            if (n > MAXN) {
                float s = __fdividef(MAXN, n);
#pragma unroll
                for (int i = 0; i < NI; i++) res[i] *= s;
                nres = MAXN;
            }
        }
        // mobius_add(res, hb) with analytic |num|^2
        float x2 = nres * nres;
        p = 0.f;
#pragma unroll
        for (int i = 0; i < NI; i++) p += res[i] * hb[lane + 32 * i];
        float xy  = wsum(p);
        float A   = 1.f + 2.f * xy + y2;
        float Bc  = 1.f - x2;
        float den = fmaxf(1.f + 2.f * xy + x2 * y2, MINN);
        float rden = __fdividef(1.f, den);
        float m[NI];
#pragma unroll
        for (int i = 0; i < NI; i++) m[i] = (A * res[i] + Bc * hb[lane + 32 * i]) * rden;
        float num2 = A * A * x2 + 2.f * A * Bc * xy + Bc * Bc * y2;
        float nm   = sqrtf(fmaxf(num2, 0.f)) * rden;
        {   // proj
            float n = fmaxf(nm, MINN);
            if (n > MAXN) {
                float s = __fdividef(MAXN, n);
#pragma unroll
                for (int i = 0; i < NI; i++) m[i] *= s;
                nm = MAXN;
            }
        }
        // relu(logmap0(.))
        float nl = fmaxf(nm, MINN);
        float la = __fdividef(artanh_(nl), nl);
        float t[NI];
#pragma unroll
        for (int i = 0; i < NI; i++) t[i] = fmaxf(la * m[i], 0.f);
        p = 0.f;
#pragma unroll
        for (int i = 0; i < NI; i++) p += t[i] * t[i];
        float tn2 = wsum(p);
        // proj(expmap0(.))
        float tn = fmaxf(sqrtf(tn2), MINN);
        float ea = __fdividef(tanhf(tn), tn);
        float no = ea * sqrtf(tn2);
#pragma unroll
        for (int i = 0; i < NI; i++) o[j][i] = ea * t[i];
        {
            float n = fmaxf(no, MINN);
            if (n > MAXN) {
                float s = __fdividef(MAXN, n);
#pragma unroll
                for (int i = 0; i < NI; i++) o[j][i] *= s;
                no = MAXN;
            }
        }
        no_out[j] = no;
    }
}

__device__ __forceinline__ int f4_nz(const float4& v) {
    return (v.x != 0.f) ? 0 : (v.y != 0.f) ? 1 : (v.z != 0.f) ? 2 : (v.w != 0.f) ? 3 : -1;
}

// ---------------- kernel 1: fused { hnn1 per agent | one-hot index extract } ----
// hnn1 blocks write g_kv in padded dim-major layout. Gather warps scan the 5
// one-hot rows of one (b,n) BIDIRECTIONALLY (front+back chunks of 128 floats),
// halving the dependent-iteration chain; all loads always in-bounds.
__global__ __launch_bounds__(256) void k_scan(
    const float* __restrict__ in_feats, const float* __restrict__ nei,
    const float* __restrict__ W1, const float* __restrict__ b1)
{
    __shared__ float sW1t[32 * 160];
    __shared__ float shb1[160];
    __shared__ float sy2;

    int t = threadIdx.x, w = t >> 5, lane = t & 31;

    if (blockIdx.x >= HNN1_BLOCKS) {
        // ---- bidirectional one-hot scan, 5 rows concurrently ----
        int bn = ((int)blockIdx.x - HNN1_BLOCKS) * 8 + w;      // [0, 8000)
        const float* rowbase = nei + (size_t)bn * (K_ * N_);
        unsigned found = 0;
        int idx[5] = {0, 0, 0, 0, 0};
#pragma unroll 1
        for (int j = 0; j < 8; j++) {
            int fj = j * 32 + lane;          // front f4 index: 0..255
            int bj = 468 - j * 32 + lane;    // back  f4 index: 244..499
            float4 fv[5], bv[5];
#pragma unroll
            for (int k = 0; k < 5; k++) {
                fv[k] = make_float4(0.f, 0.f, 0.f, 0.f);
                bv[k] = fv[k];
                if (!((found >> k) & 1)) {
                    const float4* rp = (const float4*)(rowbase + k * N_);
                    fv[k] = __ldcs(rp + fj);
                    bv[k] = __ldcs(rp + bj);
                }
            }
#pragma unroll
            for (int k = 0; k < 5; k++) {
                if ((found >> k) & 1) continue;                // warp-uniform
                int cf = f4_nz(fv[k]);
                unsigned mf = __ballot_sync(FULL, cf >= 0);
                if (mf) {
                    int s = __ffs(mf) - 1;
                    idx[k] = (j * 32 + s) * 4 + __shfl_sync(FULL, cf, s);
                    found |= 1u << k;
                    continue;
                }
                int cb = f4_nz(bv[k]);
                unsigned mb = __ballot_sync(FULL, cb >= 0);
                if (mb) {
                    int s = __ffs(mb) - 1;
                    idx[k] = (468 - j * 32 + s) * 4 + __shfl_sync(FULL, cb, s);
                    found |= 1u << k;
                }
            }
            if (found == 31u) break;
        }
        int myidx = 0;
#pragma unroll
        for (int k = 0; k < 5; k++) myidx = (lane == k) ? idx[k] : myidx;
        if (lane < 5) g_nidx[bn * 5 + lane] = myidx;
        return;
    }

    // ---- hnn1 per agent ----
    for (int i = t; i < 160 * 32; i += 256) {
        int r = i >> 5, d = i & 31;
        sW1t[d * 160 + r] = W1[i];
    }
    if (w == 0) {  // hb1 = proj(expmap0(b1))
        float bv[5]; float s = 0.f;
#pragma unroll
        for (int i = 0; i < 5; i++) { bv[i] = b1[lane + 32 * i]; s += bv[i] * bv[i]; }
        s = wsum(s);
        float n  = fmaxf(sqrtf(s), MINN);
        float e  = __fdividef(tanhf(n), n);
        float nh = e * sqrtf(s);
        float sc = e;
        float nn = fmaxf(nh, MINN);
        if (nn > MAXN) { sc *= __fdividef(MAXN, nn); nh = MAXN; }
#pragma unroll
        for (int i = 0; i < 5; i++) shb1[lane + 32 * i] = sc * bv[i];
        if (lane == 0) sy2 = nh * nh;
    }
    __syncthreads();
    float y2 = sy2;

    int row00 = ((int)blockIdx.x * 8 + w) * 4;     // 4 rows per warp, J=2 twice
#pragma unroll 1
    for (int jj = 0; jj < 2; jj++) {
        int row0 = row00 + jj * 2;
        float x[2], xn2[2];
#pragma unroll
        for (int j = 0; j < 2; j++) {
            float u  = in_feats[(size_t)(row0 + j) * 32 + lane];
            float n2 = wsum(u * u);
            float n  = fmaxf(sqrtf(n2), MINN);
            float f  = __fdividef(artanh_(n), n) * u;   // logmap0
            x[j] = ball_point(f, xn2[j]);               // proj(expmap0(.))
        }
        float o[2][5], no[2];
        hnn_batch<2, 5>(sW1t, shb1, y2, x, xn2, lane, o, no);
#pragma unroll
        for (int j = 0; j < 2; j++) {
            float n  = fmaxf(no[j], MINN);
            float ql = __fdividef(artanh_(n), n);       // final logmap0 scale
#pragma unroll
            for (int i = 0; i < 5; i++) {
                int r = lane + 32 * i;             // element r = d*5+h
                int d = r / 5, h = r - 5 * d;
                g_kv[(size_t)(row0 + j) * KV_STRIDE + d * 8 + h] = ql * o[j][i];
            }
        }
    }
}

// ---------------- kernel 2: attention + final hnn layer -------------------------
// One warp per (b,n). Dim-major padded g_kv: lane=dim loads its 5 head values
// with one float4 + one float.
__global__ __launch_bounds__(256) void k_att(
    const float* __restrict__ W2, const float* __restrict__ b2,
    float* __restrict__ out, float* __restrict__ att_out)
{
    __shared__ float sW2t[32 * 32];
    __shared__ float shb2[32];
    __shared__ float sy2;

    int t = threadIdx.x, w = t >> 5, lane = t & 31;
    for (int i = t; i < 32 * 32; i += 256) {
        int r = i >> 5, d = i & 31;
        sW2t[d * 32 + r] = W2[i];
    }
    if (w == 0) {  // hb2 = proj(expmap0(b2))
        float bv = b2[lane];
        float s  = wsum(bv * bv);
        float n  = fmaxf(sqrtf(s), MINN);
        float e  = __fdividef(tanhf(n), n);
        float nh = e * sqrtf(s);
        float sc = e;
        float nn = fmaxf(nh, MINN);
        if (nn > MAXN) { sc *= __fdividef(MAXN, nn); nh = MAXN; }
        shb2[lane] = sc * bv;
        if (lane == 0) sy2 = nh * nh;
    }
    __syncthreads();
    float y2 = sy2;

    int row = (int)blockIdx.x * 8 + w;             // grid = ROWS/8 exactly
    int b   = row / N_;

    float q[5];
    {
        const float* p = g_kv + (size_t)row * KV_STRIDE + lane * 8;
        float4 v = *(const float4*)p;
        q[0] = v.x; q[1] = v.y; q[2] = v.z; q[3] = v.w; q[4] = p[4];
    }

    int nv = (lane < 5) ? g_nidx[row * 5 + lane] : 0;
    float kvr[5][5];
#pragma unroll
    for (int k = 0; k < 5; k++) {
        int m = __shfl_sync(FULL, nv, k);
        const float* p = g_kv + (size_t)(b * N_ + m) * KV_STRIDE + lane * 8;
        float4 v = *(const float4*)p;
        kvr[k][0] = v.x; kvr[k][1] = v.y; kvr[k][2] = v.z; kvr[k][3] = v.w;
        kvr[k][4] = p[4];
    }

    // logits[h][k] = sum_d q[h,d]*kv[k][h,d]  (d = lanes)
    float lg[25];
#pragma unroll
    for (int h = 0; h < 5; h++)
#pragma unroll
        for (int k = 0; k < 5; k++)
            lg[h * 5 + k] = wsum(q[h] * kvr[k][h]);

    // softmax over k per head, in place (warp-uniform)
#pragma unroll
    for (int h = 0; h < 5; h++) {
        float mxv = lg[h * 5];
#pragma unroll
        for (int k = 1; k < 5; k++) mxv = fmaxf(mxv, lg[h * 5 + k]);
        float s = 0.f;
#pragma unroll
        for (int k = 0; k < 5; k++) { float ev = __expf(lg[h * 5 + k] - mxv); lg[h * 5 + k] = ev; s += ev; }
        float inv = __fdividef(1.f, s);
#pragma unroll
        for (int k = 0; k < 5; k++) lg[h * 5 + k] *= inv;
    }

    if (att_out) {  // att_record[row, h, k]; lane <-> h*5+k
        float val = 0.f;
#pragma unroll
        for (int e = 0; e < 25; e++) val = (lane == e) ? lg[e] : val;
        if (lane < 25) att_out[(size_t)row * 25 + lane] = val;
    }

    // out[d=lane] = (1/5) * sum_h sum_k att[h,k]*kv[k][h,lane]
    float od = 0.f;
#pragma unroll
    for (int h = 0; h < 5; h++) {
        float s = 0.f;
#pragma unroll
        for (int k = 0; k < 5; k++) s = fmaf(lg[h * 5 + k], kvr[k][h], s);
        od += s;
    }
    od *= 0.2f;

    // proj(expmap0(out)) -> hnn_layer(W2, b2)
    float xr[1], xn2[1];
    xr[0] = ball_point(od, xn2[0]);
    float o[1][1], no[1];
    hnn_batch<1, 1>(sW2t, shb2, y2, xr, xn2, lane, o, no);
    out[(size_t)row * 32 + lane] = o[0][0];
}

// ---------------- launch ----------------
extern "C" void kernel_launch(void* const* d_in, const int* in_sizes, int n_in,
                              void* d_out, int out_size) {
    const float* in_feats = (const float*)d_in[0];
    const float* in_nei   = (const float*)d_in[1];
    const float* W1       = (const float*)d_in[2];
    const float* b1       = (const float*)d_in[3];
    const float* W2       = (const float*)d_in[4];
    const float* b2       = (const float*)d_in[5];
    float* out = (float*)d_out;
    // out (B*N*32 = 256000) followed by att_record (B*N*5*5 = 200000), if present.
    float* att = (out_size >= ROWS * 32 + ROWS * 25) ? (out + ROWS * 32) : nullptr;

    k_scan<<<HNN1_BLOCKS + GATHER_BLOCKS, 256>>>(in_feats, in_nei, W1, b1);
    k_att<<<ROWS / 8, 256>>>(W2, b2, out, att);
}

// round 11
// speedup vs baseline: 2.5037x; 1.0243x over previous
#include <cuda_runtime.h>
#include <math.h>

#define FULL 0xffffffffu

static constexpr int B_    = 4;
static constexpr int N_    = 2000;
static constexpr int K_    = 5;
static constexpr int ROWS  = B_ * N_;           // 8000
static constexpr float MINN = 1e-15f;
static constexpr float MAXN = 1.0f - 4e-3f;     // (1-EPS)/sqrt(c), c=1

static constexpr int HNN1_BLOCKS   = 250;       // 8 warps x 4 rows = 32 rows/block
static constexpr int GATHER_BLOCKS = ROWS / 8;  // 1000: one warp per (b,n), 5 rows each
static constexpr int KV_STRIDE     = 256;       // padded: [row][d*8 + h]

// ---------------- scratch (no allocation allowed) ----------------
__device__ int   g_nidx[ROWS * K_];             // neighbor index per (b,n,k)
__device__ float g_kv[ROWS * KV_STRIDE];        // hnn1 output, dim-major padded (8.2 MB)

// ---------------- helpers ----------------
__device__ __forceinline__ float wsum(float v) {
#pragma unroll
    for (int o = 16; o; o >>= 1) v += __shfl_xor_sync(FULL, v, o);
    return v;
}

// artanh via single fast log: 0.5*log((1+x)/(1-x)). Rel err ~1e-6 (vs 1e-3 budget).
__device__ __forceinline__ float artanh_(float x) {
    x = fminf(fmaxf(x, -1.0f + 1e-7f), 1.0f - 1e-7f);
    return 0.5f * __logf(__fdividef(1.0f + x, 1.0f - x));
}

// proj(expmap0(u)) for a 32-d tangent vector (lane = dim).
__device__ __forceinline__ float ball_point(float u, float& np2) {
    float n2 = wsum(u * u);
    float n  = fmaxf(sqrtf(n2), MINN);
    float e  = __fdividef(tanhf(n), n);
    float pv = e * u;
    float np = e * sqrtf(n2);
    float nn = fmaxf(np, MINN);
    if (nn > MAXN) { pv *= __fdividef(MAXN, nn); np = MAXN; }
    np2 = np * np;
    return pv;
}

// Full hnn_layer for J points (amortizes W smem reads J-fold).
// x[j] broadcast via shfl; output row r = lane + 32*i; Wt[d*NI*32 + r] in smem.
template <int J, int NI>
__device__ __forceinline__ void hnn_batch(
    const float* Wt, const float* hb, float y2,
    const float x[J], const float xn2a[J], int lane,
    float o[J][NI], float no_out[J])
{
    float mx[J][NI];
#pragma unroll
    for (int j = 0; j < J; j++)
#pragma unroll
        for (int i = 0; i < NI; i++) mx[j][i] = 0.f;

#pragma unroll
    for (int d = 0; d < 32; d++) {
        float wv[NI];
#pragma unroll
        for (int i = 0; i < NI; i++) wv[i] = Wt[d * NI * 32 + lane + 32 * i];
#pragma unroll
        for (int j = 0; j < J; j++) {
            float xd = __shfl_sync(FULL, x[j], d);
#pragma unroll
            for (int i = 0; i < NI; i++) mx[j][i] = fmaf(wv[i], xd, mx[j][i]);
        }
    }

#pragma unroll
    for (int j = 0; j < J; j++) {
        float p = 0.f;
#pragma unroll
        for (int i = 0; i < NI; i++) p += mx[j][i] * mx[j][i];
        float mxn2 = wsum(p);
        float xn  = fmaxf(sqrtf(xn2a[j]), MINN);
        float mxn = fmaxf(sqrtf(mxn2), MINN);
        float r   = tanhf(__fdividef(mxn, xn) * artanh_(xn));

        float res[NI]; float nres;
        if (mxn2 == 0.f) {
#pragma unroll
            for (int i = 0; i < NI; i++) res[i] = 0.f;
            nres = 0.f;
        } else {
            float s = __fdividef(r, mxn);
#pragma unroll
            for (int i = 0; i < NI; i++) res[i] = mx[j][i] * s;
            nres = r;
        }
        {   // proj
            float n = fmaxf(nres, MINN);
            if (n > MAXN) {
                float s = __fdividef(MAXN, n);
#pragma unroll
                for (int i = 0; i < NI; i++) res[i] *= s;
                nres = MAXN;
            }
        }
        // mobius_add(res, hb) with analytic |num|^2
        float x2 = nres * nres;
        p = 0.f;
#pragma unroll
        for (int i = 0; i < NI; i++) p += res[i] * hb[lane + 32 * i];
        float xy  = wsum(p);
        float A   = 1.f + 2.f * xy + y2;
        float Bc  = 1.f - x2;
        float den = fmaxf(1.f + 2.f * xy + x2 * y2, MINN);
        float rden = __fdividef(1.f, den);
        float m[NI];
#pragma unroll
        for (int i = 0; i < NI; i++) m[i] = (A * res[i] + Bc * hb[lane + 32 * i]) * rden;
        float num2 = A * A * x2 + 2.f * A * Bc * xy + Bc * Bc * y2;
        float nm   = sqrtf(fmaxf(num2, 0.f)) * rden;
        {   // proj
            float n = fmaxf(nm, MINN);
            if (n > MAXN) {
                float s = __fdividef(MAXN, n);
#pragma unroll
                for (int i = 0; i < NI; i++) m[i] *= s;
                nm = MAXN;
            }
        }
        // relu(logmap0(.))
        float nl = fmaxf(nm, MINN);
        float la = __fdividef(artanh_(nl), nl);
        float t[NI];
#pragma unroll
        for (int i = 0; i < NI; i++) t[i] = fmaxf(la * m[i], 0.f);
        p = 0.f;
#pragma unroll
        for (int i = 0; i < NI; i++) p += t[i] * t[i];
        float tn2 = wsum(p);
        // proj(expmap0(.))
        float tn = fmaxf(sqrtf(tn2), MINN);
        float ea = __fdividef(tanhf(tn), tn);
        float no = ea * sqrtf(tn2);
#pragma unroll
        for (int i = 0; i < NI; i++) o[j][i] = ea * t[i];
        {
            float n = fmaxf(no, MINN);
            if (n > MAXN) {
                float s = __fdividef(MAXN, n);
#pragma unroll
                for (int i = 0; i < NI; i++) o[j][i] *= s;
                no = MAXN;
            }
        }
        no_out[j] = no;
    }
}

__device__ __forceinline__ int f4_nz(const float4& v) {
    return (v.x != 0.f) ? 0 : (v.y != 0.f) ? 1 : (v.z != 0.f) ? 2 : (v.w != 0.f) ? 3 : -1;
}

// ---------------- kernel 1: fused { hnn1 per agent | one-hot index extract } ----
// Gather warps: lanes 0-15 scan a 64-float front chunk, lanes 16-31 the matching
// back chunk, one load + one ballot per row per iteration (C=64 per side).
// launch_bounds(256,4) caps regs at 64 -> 32 warps/SM for the DRAM stream.
__global__ __launch_bounds__(256, 4) void k_scan(
    const float* __restrict__ in_feats, const float* __restrict__ nei,
    const float* __restrict__ W1, const float* __restrict__ b1)
{
    __shared__ float sW1t[32 * 160];
    __shared__ float shb1[160];
    __shared__ float sy2;

    int t = threadIdx.x, w = t >> 5, lane = t & 31;

    if (blockIdx.x >= HNN1_BLOCKS) {
        // ---- bidirectional one-hot scan, half-warp per side, 5 rows ----
        int bn = ((int)blockIdx.x - HNN1_BLOCKS) * 8 + w;      // [0, 8000)
        const float* rowbase = nei + (size_t)bn * (K_ * N_);
        bool fr = lane < 16;
        unsigned found = 0;
        int idx[5] = {0, 0, 0, 0, 0};
#pragma unroll 1
        for (int j = 0; j < 16; j++) {
            // front f4: j*16 + lane (lanes 0-15); back f4: 484 - j*16 + (lane-16)
            int f4i = fr ? (j * 16 + lane) : (468 - j * 16 + lane);
            float4 v[5];
#pragma unroll
            for (int k = 0; k < 5; k++) {
                v[k] = make_float4(0.f, 0.f, 0.f, 0.f);
                if (!((found >> k) & 1))
                    v[k] = __ldcs((const float4*)(rowbase + k * N_) + f4i);
            }
#pragma unroll
            for (int k = 0; k < 5; k++) {
                if ((found >> k) & 1) continue;                // warp-uniform
                int c = f4_nz(v[k]);
                unsigned m = __ballot_sync(FULL, c >= 0);
                if (m) {
                    int s = __ffs(m) - 1;
                    int cc = __shfl_sync(FULL, c, s);
                    int f4pos = (s < 16) ? (j * 16 + s) : (468 - j * 16 + s);
                    idx[k] = f4pos * 4 + cc;
                    found |= 1u << k;
                }
            }
            if (found == 31u) break;
        }
        int myidx = 0;
#pragma unroll
        for (int k = 0; k < 5; k++) myidx = (lane == k) ? idx[k] : myidx;
        if (lane < 5) g_nidx[bn * 5 + lane] = myidx;
        return;
    }

    // ---- hnn1 per agent ----
    for (int i = t; i < 160 * 32; i += 256) {
        int r = i >> 5, d = i & 31;
        sW1t[d * 160 + r] = W1[i];
    }
    if (w == 0) {  // hb1 = proj(expmap0(b1))
        float bv[5]; float s = 0.f;
#pragma unroll
        for (int i = 0; i < 5; i++) { bv[i] = b1[lane + 32 * i]; s += bv[i] * bv[i]; }
        s = wsum(s);
        float n  = fmaxf(sqrtf(s), MINN);
        float e  = __fdividef(tanhf(n), n);
        float nh = e * sqrtf(s);
        float sc = e;
        float nn = fmaxf(nh, MINN);
        if (nn > MAXN) { sc *= __fdividef(MAXN, nn); nh = MAXN; }
#pragma unroll
        for (int i = 0; i < 5; i++) shb1[lane + 32 * i] = sc * bv[i];
        if (lane == 0) sy2 = nh * nh;
    }
    __syncthreads();
    float y2 = sy2;

    int row00 = ((int)blockIdx.x * 8 + w) * 4;     // 4 rows per warp, J=2 twice
#pragma unroll 1
    for (int jj = 0; jj < 2; jj++) {
        int row0 = row00 + jj * 2;
        float x[2], xn2[2];
#pragma unroll
        for (int j = 0; j < 2; j++) {
            float u  = in_feats[(size_t)(row0 + j) * 32 + lane];
            float n2 = wsum(u * u);
            float n  = fmaxf(sqrtf(n2), MINN);
            float f  = __fdividef(artanh_(n), n) * u;   // logmap0
            x[j] = ball_point(f, xn2[j]);               // proj(expmap0(.))
        }
        float o[2][5], no[2];
        hnn_batch<2, 5>(sW1t, shb1, y2, x, xn2, lane, o, no);
#pragma unroll
        for (int j = 0; j < 2; j++) {
            float n  = fmaxf(no[j], MINN);
            float ql = __fdividef(artanh_(n), n);       // final logmap0 scale
#pragma unroll
            for (int i = 0; i < 5; i++) {
                int r = lane + 32 * i;             // element r = d*5+h
                int d = r / 5, h = r - 5 * d;
                g_kv[(size_t)(row0 + j) * KV_STRIDE + d * 8 + h] = ql * o[j][i];
            }
        }
    }
}

// ---------------- kernel 2: attention + final hnn layer -------------------------
// One warp per (b,n). Logits via 31-shuffle reduce-scatter tree (lane e owns
// logit e=h*5+k), group-of-5 softmax per lane (1 exp), 25-shuffle broadcast.
__global__ __launch_bounds__(256) void k_att(
    const float* __restrict__ W2, const float* __restrict__ b2,
    float* __restrict__ out, float* __restrict__ att_out)
{
    __shared__ float sW2t[32 * 32];
    __shared__ float shb2[32];
    __shared__ float sy2;

    int t = threadIdx.x, w = t >> 5, lane = t & 31;
    for (int i = t; i < 32 * 32; i += 256) {
        int r = i >> 5, d = i & 31;
        sW2t[d * 32 + r] = W2[i];
    }
    if (w == 0) {  // hb2 = proj(expmap0(b2))
        float bv = b2[lane];
        float s  = wsum(bv * bv);
        float n  = fmaxf(sqrtf(s), MINN);
        float e  = __fdividef(tanhf(n), n);
        float nh = e * sqrtf(s);
        float sc = e;
        float nn = fmaxf(nh, MINN);
        if (nn > MAXN) { sc *= __fdividef(MAXN, nn); nh = MAXN; }
        shb2[lane] = sc * bv;
        if (lane == 0) sy2 = nh * nh;
    }
    __syncthreads();
    float y2 = sy2;

    int row = (int)blockIdx.x * 8 + w;             // grid = ROWS/8 exactly
    int b   = row / N_;

    float q[5];
    {
        const float* p = g_kv + (size_t)row * KV_STRIDE + lane * 8;
        float4 v4 = *(const float4*)p;
        q[0] = v4.x; q[1] = v4.y; q[2] = v4.z; q[3] = v4.w; q[4] = p[4];
    }

    int nv = (lane < 5) ? g_nidx[row * 5 + lane] : 0;
    float kvr[5][5];
#pragma unroll
    for (int k = 0; k < 5; k++) {
        int m = __shfl_sync(FULL, nv, k);
        const float* p = g_kv + (size_t)(b * N_ + m) * KV_STRIDE + lane * 8;
        float4 v4 = *(const float4*)p;
        kvr[k][0] = v4.x; kvr[k][1] = v4.y; kvr[k][2] = v4.z; kvr[k][3] = v4.w;
        kvr[k][4] = p[4];
    }

    // per-lane partial products for all 25 logits
    float v[25];
#pragma unroll
    for (int h = 0; h < 5; h++)
#pragma unroll
        for (int k = 0; k < 5; k++) v[h * 5 + k] = q[h] * kvr[k][h];

    // reduce-scatter tree: after 5 steps lane e holds logit e (e<25); 31 shuffles
    {   // step o=16 with implicit zero padding for e in [25,32)
        bool hi = (lane & 16) != 0;
#pragma unroll
        for (int i = 0; i < 16; i++) {
            float vh = (i + 16 < 25) ? v[i + 16] : 0.f;
            float send = hi ? v[i] : vh;
            float recv = __shfl_xor_sync(FULL, send, 16);
            v[i] = (hi ? vh : v[i]) + recv;
        }
    }
#pragma unroll
    for (int step = 1; step < 5; step++) {
        int o = 16 >> step;
        bool hi = (lane & o) != 0;
#pragma unroll
        for (int i = 0; i < (16 >> step); i++) {
            float send = hi ? v[i] : v[i + (16 >> step)];
            float recv = __shfl_xor_sync(FULL, send, o);
            v[i] = (hi ? v[i + (16 >> step)] : v[i]) + recv;
        }
    }
    float mylg = v[0];

    // softmax over k within each lane-group of 5 (lanes 5h..5h+4)
    int gbase = (lane / 5) * 5;
    float mx = mylg;
#pragma unroll
    for (int j2 = 0; j2 < 5; j2++) mx = fmaxf(mx, __shfl_sync(FULL, mylg, gbase + j2));
    float ex = __expf(mylg - mx);
    float sm = 0.f;
#pragma unroll
    for (int j2 = 0; j2 < 5; j2++) sm += __shfl_sync(FULL, ex, gbase + j2);
    float attl = __fdividef(ex, sm);

    if (att_out && lane < 25) att_out[(size_t)row * 25 + lane] = attl;

    // broadcast attention weights to all lanes
    float attb[25];
#pragma unroll
    for (int e = 0; e < 25; e++) attb[e] = __shfl_sync(FULL, attl, e);

    // out[d=lane] = (1/5) * sum_h sum_k att[h,k]*kv[k][h,lane]
    float od = 0.f;
#pragma unroll
    for (int h = 0; h < 5; h++) {
        float s = 0.f;
#pragma unroll
        for (int k = 0; k < 5; k++) s = fmaf(attb[h * 5 + k], kvr[k][h], s);
        od += s;
    }
    od *= 0.2f;

    // proj(expmap0(out)) -> hnn_layer(W2, b2)
    float xr[1], xn2[1];
    xr[0] = ball_point(od, xn2[0]);
    float o[1][1], no[1];
    hnn_batch<1, 1>(sW2t, shb2, y2, xr, xn2, lane, o, no);
    out[(size_t)row * 32 + lane] = o[0][0];
}

// ---------------- launch ----------------
extern "C" void kernel_launch(void* const* d_in, const int* in_sizes, int n_in,
                              void* d_out, int out_size) {
    const float* in_feats = (const float*)d_in[0];
    const float* in_nei   = (const float*)d_in[1];
    const float* W1       = (const float*)d_in[2];
    const float* b1       = (const float*)d_in[3];
    const float* W2       = (const float*)d_in[4];
    const float* b2       = (const float*)d_in[5];
    float* out = (float*)d_out;
    // out (B*N*32 = 256000) followed by att_record (B*N*5*5 = 200000), if present.
    float* att = (out_size >= ROWS * 32 + ROWS * 25) ? (out + ROWS * 32) : nullptr;

    k_scan<<<HNN1_BLOCKS + GATHER_BLOCKS, 256>>>(in_feats, in_nei, W1, b1);
    k_att<<<ROWS / 8, 256>>>(W2, b2, out, att);
}

// round 16
// speedup vs baseline: 2.5137x; 1.0040x over previous
#include <cuda_runtime.h>
#include <math.h>

#define FULL 0xffffffffu

static constexpr int B_    = 4;
static constexpr int N_    = 2000;
static constexpr int K_    = 5;
static constexpr int ROWS  = B_ * N_;           // 8000
static constexpr float MINN = 1e-15f;
static constexpr float MAXN = 1.0f - 4e-3f;     // (1-EPS)/sqrt(c), c=1

static constexpr int HNN1_BLOCKS   = 250;       // 8 warps x 4 rows = 32 rows/block
static constexpr int GATHER_BLOCKS = ROWS / 8;  // 1000: one warp per (b,n)
static constexpr int KV_STRIDE     = 256;       // padded: [row][d*8 + h]

// ---------------- scratch (no allocation allowed) ----------------
__device__ float g_kv[ROWS * KV_STRIDE];        // hnn1 output, dim-major padded (8.2 MB)
__device__ int   g_done = 0;                    // hnn1 completion counter

// ---------------- helpers ----------------
__device__ __forceinline__ float wsum(float v) {
#pragma unroll
    for (int o = 16; o; o >>= 1) v += __shfl_xor_sync(FULL, v, o);
    return v;
}

// artanh via single fast log: 0.5*log((1+x)/(1-x)). Rel err ~1e-6 (vs 1e-3 budget).
__device__ __forceinline__ float artanh_(float x) {
    x = fminf(fmaxf(x, -1.0f + 1e-7f), 1.0f - 1e-7f);
    return 0.5f * __logf(__fdividef(1.0f + x, 1.0f - x));
}

// proj(expmap0(u)) for a 32-d tangent vector (lane = dim).
__device__ __forceinline__ float ball_point(float u, float& np2) {
    float n2 = wsum(u * u);
    float n  = fmaxf(sqrtf(n2), MINN);
    float e  = __fdividef(tanhf(n), n);
    float pv = e * u;
    float np = e * sqrtf(n2);
    float nn = fmaxf(np, MINN);
    if (nn > MAXN) { pv *= __fdividef(MAXN, nn); np = MAXN; }
    np2 = np * np;
    return pv;
}

// Full hnn_layer for J points (amortizes W smem reads J-fold).
template <int J, int NI>
__device__ __forceinline__ void hnn_batch(
    const float* Wt, const float* hb, float y2,
    const float x[J], const float xn2a[J], int lane,
    float o[J][NI], float no_out[J])
{
    float mx[J][NI];
#pragma unroll
    for (int j = 0; j < J; j++)
#pragma unroll
        for (int i = 0; i < NI; i++) mx[j][i] = 0.f;

#pragma unroll
    for (int d = 0; d < 32; d++) {
        float wv[NI];
#pragma unroll
        for (int i = 0; i < NI; i++) wv[i] = Wt[d * NI * 32 + lane + 32 * i];
#pragma unroll
        for (int j = 0; j < J; j++) {
            float xd = __shfl_sync(FULL, x[j], d);
#pragma unroll
            for (int i = 0; i < NI; i++) mx[j][i] = fmaf(wv[i], xd, mx[j][i]);
        }
    }

#pragma unroll
    for (int j = 0; j < J; j++) {
        float p = 0.f;
#pragma unroll
        for (int i = 0; i < NI; i++) p += mx[j][i] * mx[j][i];
        float mxn2 = wsum(p);
        float xn  = fmaxf(sqrtf(xn2a[j]), MINN);
        float mxn = fmaxf(sqrtf(mxn2), MINN);
        float r   = tanhf(__fdividef(mxn, xn) * artanh_(xn));

        float res[NI]; float nres;
        if (mxn2 == 0.f) {
#pragma unroll
            for (int i = 0; i < NI; i++) res[i] = 0.f;
            nres = 0.f;
        } else {
            float s = __fdividef(r, mxn);
#pragma unroll
            for (int i = 0; i < NI; i++) res[i] = mx[j][i] * s;
            nres = r;
        }
        {   // proj
            float n = fmaxf(nres, MINN);
            if (n > MAXN) {
                float s = __fdividef(MAXN, n);
#pragma unroll
                for (int i = 0; i < NI; i++) res[i] *= s;
                nres = MAXN;
            }
        }
        // mobius_add(res, hb) with analytic |num|^2
        float x2 = nres * nres;
        p = 0.f;
#pragma unroll
        for (int i = 0; i < NI; i++) p += res[i] * hb[lane + 32 * i];
        float xy  = wsum(p);
        float A   = 1.f + 2.f * xy + y2;
        float Bc  = 1.f - x2;
        float den = fmaxf(1.f + 2.f * xy + x2 * y2, MINN);
        float rden = __fdividef(1.f, den);
        float m[NI];
#pragma unroll
        for (int i = 0; i < NI; i++) m[i] = (A * res[i] + Bc * hb[lane + 32 * i]) * rden;
        float num2 = A * A * x2 + 2.f * A * Bc * xy + Bc * Bc * y2;
        float nm   = sqrtf(fmaxf(num2, 0.f)) * rden;
        {   // proj
            float n = fmaxf(nm, MINN);
            if (n > MAXN) {
                float s = __fdividef(MAXN, n);
#pragma unroll
                for (int i = 0; i < NI; i++) m[i] *= s;
                nm = MAXN;
            }
        }
        // relu(logmap0(.))
        float nl = fmaxf(nm, MINN);
        float la = __fdividef(artanh_(nl), nl);
        float t[NI];
#pragma unroll
        for (int i = 0; i < NI; i++) t[i] = fmaxf(la * m[i], 0.f);
        p = 0.f;
#pragma unroll
        for (int i = 0; i < NI; i++) p += t[i] * t[i];
        float tn2 = wsum(p);
        // proj(expmap0(.))
        float tn = fmaxf(sqrtf(tn2), MINN);
        float ea = __fdividef(tanhf(tn), tn);
        float no = ea * sqrtf(tn2);
#pragma unroll
        for (int i = 0; i < NI; i++) o[j][i] = ea * t[i];
        {
            float n = fmaxf(no, MINN);
            if (n > MAXN) {
                float s = __fdividef(MAXN, n);
#pragma unroll
                for (int i = 0; i < NI; i++) o[j][i] *= s;
                no = MAXN;
            }
        }
        no_out[j] = no;
    }
}

__device__ __forceinline__ int f4_nz(const float4& v) {
    return (v.x != 0.f) ? 0 : (v.y != 0.f) ? 1 : (v.z != 0.f) ? 2 : (v.w != 0.f) ? 3 : -1;
}

// ---------------- single fused kernel -------------------------------------------
// Blocks [0, 250): hnn1 for all 8000 agents -> g_kv; release g_done.
// Blocks [250, 1250): one warp per (b,n): bidirectional one-hot scan of its 5
// rows (software-pipelined), spin on g_done (hnn1 finishes ~3us in, scans take
// ~30us -> gate is free), then attention + final hnn layer for that row.
__global__ __launch_bounds__(256, 3) void k_all(
    const float* __restrict__ in_feats, const float* __restrict__ nei,
    const float* __restrict__ W1, const float* __restrict__ b1,
    const float* __restrict__ W2, const float* __restrict__ b2,
    float* __restrict__ out, float* __restrict__ att_out)
{
    __shared__ float sW1t[32 * 160];
    __shared__ float shb1[160];
    __shared__ float sy1;
    __shared__ float sW2t[32 * 32];
    __shared__ float shb2[32];
    __shared__ float sy2b;

    int t = threadIdx.x, w = t >> 5, lane = t & 31;

    if (blockIdx.x < HNN1_BLOCKS) {
        // ================= hnn1 phase =================
        for (int i = t; i < 160 * 32; i += 256) {
            int r = i >> 5, d = i & 31;
            sW1t[d * 160 + r] = W1[i];
        }
        if (w == 0) {  // hb1 = proj(expmap0(b1))
            float bv[5]; float s = 0.f;
#pragma unroll
            for (int i = 0; i < 5; i++) { bv[i] = b1[lane + 32 * i]; s += bv[i] * bv[i]; }
            s = wsum(s);
            float n  = fmaxf(sqrtf(s), MINN);
            float e  = __fdividef(tanhf(n), n);
            float nh = e * sqrtf(s);
            float sc = e;
            float nn = fmaxf(nh, MINN);
            if (nn > MAXN) { sc *= __fdividef(MAXN, nn); nh = MAXN; }
#pragma unroll
            for (int i = 0; i < 5; i++) shb1[lane + 32 * i] = sc * bv[i];
            if (lane == 0) sy1 = nh * nh;
        }
        __syncthreads();
        float y2 = sy1;

        int row00 = ((int)blockIdx.x * 8 + w) * 4;     // 4 rows per warp, J=2 twice
#pragma unroll 1
        for (int jj = 0; jj < 2; jj++) {
            int row0 = row00 + jj * 2;
            float x[2], xn2[2];
#pragma unroll
            for (int j = 0; j < 2; j++) {
                float u  = in_feats[(size_t)(row0 + j) * 32 + lane];
                float n2 = wsum(u * u);
                float n  = fmaxf(sqrtf(n2), MINN);
                float f  = __fdividef(artanh_(n), n) * u;   // logmap0
                x[j] = ball_point(f, xn2[j]);               // proj(expmap0(.))
            }
            float o[2][5], no[2];
            hnn_batch<2, 5>(sW1t, shb1, y2, x, xn2, lane, o, no);
#pragma unroll
            for (int j = 0; j < 2; j++) {
                float n  = fmaxf(no[j], MINN);
                float ql = __fdividef(artanh_(n), n);       // final logmap0 scale
#pragma unroll
                for (int i = 0; i < 5; i++) {
                    int r = lane + 32 * i;             // element r = d*5+h
                    int d = r / 5, h = r - 5 * d;
                    g_kv[(size_t)(row0 + j) * KV_STRIDE + d * 8 + h] = ql * o[j][i];
                }
            }
        }
        __syncthreads();
        if (t == 0) { __threadfence(); atomicAdd(&g_done, 1); }   // release
        return;
    }

    // ================= gather + attention phase =================
    for (int i = t; i < 32 * 32; i += 256) {
        int r = i >> 5, d = i & 31;
        sW2t[d * 32 + r] = W2[i];
    }
    if (w == 0) {  // hb2 = proj(expmap0(b2))
        float bv = b2[lane];
        float s  = wsum(bv * bv);
        float n  = fmaxf(sqrtf(s), MINN);
        float e  = __fdividef(tanhf(n), n);
        float nh = e * sqrtf(s);
        float sc = e;
        float nn = fmaxf(nh, MINN);
        if (nn > MAXN) { sc *= __fdividef(MAXN, nn); nh = MAXN; }
        shb2[lane] = sc * bv;
        if (lane == 0) sy2b = nh * nh;
    }
    __syncthreads();
    float y2b = sy2b;

    int bn = ((int)blockIdx.x - HNN1_BLOCKS) * 8 + w;      // [0, 8000)
    const float* rowbase = nei + (size_t)bn * (K_ * N_);
    bool fr = lane < 16;

    // ---- software-pipelined bidirectional one-hot scan (half-warp per side) ----
    unsigned found = 0;
    int idx[5] = {0, 0, 0, 0, 0};
    float4 v[5];
    {
        int f4i = fr ? lane : (468 + lane);
#pragma unroll
        for (int k = 0; k < 5; k++)
            v[k] = __ldcs((const float4*)(rowbase + k * N_) + f4i);
    }
#pragma unroll 1
    for (int j = 0; j < 16; j++) {
        float4 vn[5];
        if (j < 15) {   // preload next chunk (predicated on stale mask; extra reads ok)
            int f4n = fr ? ((j + 1) * 16 + lane) : (468 - (j + 1) * 16 + lane);
#pragma unroll
            for (int k = 0; k < 5; k++) {
                vn[k] = make_float4(0.f, 0.f, 0.f, 0.f);
                if (!((found >> k) & 1))
                    vn[k] = __ldcs((const float4*)(rowbase + k * N_) + f4n);
            }
        }
#pragma unroll
        for (int k = 0; k < 5; k++) {
            if ((found >> k) & 1) continue;                // warp-uniform
            int c = f4_nz(v[k]);
            unsigned m = __ballot_sync(FULL, c >= 0);
            if (m) {
                int s = __ffs(m) - 1;
                int cc = __shfl_sync(FULL, c, s);
                int f4pos = (s < 16) ? (j * 16 + s) : (468 - j * 16 + s);
                idx[k] = f4pos * 4 + cc;                   // warp-uniform value
                found |= 1u << k;
            }
        }
        if (found == 31u) break;
#pragma unroll
        for (int k = 0; k < 5; k++) v[k] = vn[k];
    }

    // ---- gate: wait for all hnn1 blocks (normally already done) ----
    while (*(volatile int*)&g_done < HNN1_BLOCKS) __nanosleep(128);
    __threadfence();                                        // acquire
    __syncwarp();

    // ---- attention ----
    int b = bn / N_;
    float q[5];
    {
        const float* p = g_kv + (size_t)bn * KV_STRIDE + lane * 8;
        float4 v4 = *(const float4*)p;
        q[0] = v4.x; q[1] = v4.y; q[2] = v4.z; q[3] = v4.w; q[4] = p[4];
    }
    float kvr[5][5];
#pragma unroll
    for (int k = 0; k < 5; k++) {
        const float* p = g_kv + (size_t)(b * N_ + idx[k]) * KV_STRIDE + lane * 8;
        float4 v4 = *(const float4*)p;
        kvr[k][0] = v4.x; kvr[k][1] = v4.y; kvr[k][2] = v4.z; kvr[k][3] = v4.w;
        kvr[k][4] = p[4];
    }

    // per-lane partial products for all 25 logits
    float pv[25];
#pragma unroll
    for (int h = 0; h < 5; h++)
#pragma unroll
        for (int k = 0; k < 5; k++) pv[h * 5 + k] = q[h] * kvr[k][h];

    // reduce-scatter tree: after 5 steps lane e holds logit e (e<25)
    {
        bool hi = (lane & 16) != 0;
#pragma unroll
        for (int i = 0; i < 16; i++) {
            float vh = (i + 16 < 25) ? pv[i + 16] : 0.f;
            float send = hi ? pv[i] : vh;
            float recv = __shfl_xor_sync(FULL, send, 16);
            pv[i] = (hi ? vh : pv[i]) + recv;
        }
    }
#pragma unroll
    for (int step = 1; step < 5; step++) {
        int o = 16 >> step;
        bool hi = (lane & o) != 0;
#pragma unroll
        for (int i = 0; i < (16 >> step); i++) {
            float send = hi ? pv[i] : pv[i + (16 >> step)];
            float recv = __shfl_xor_sync(FULL, send, o);
            pv[i] = (hi ? pv[i + (16 >> step)] : pv[i]) + recv;
        }
    }
    float mylg = pv[0];

    // softmax over k within each lane-group of 5 (lanes 5h..5h+4)
    int gbase = (lane / 5) * 5;
    float mx = mylg;
#pragma unroll
    for (int j2 = 0; j2 < 5; j2++) mx = fmaxf(mx, __shfl_sync(FULL, mylg, gbase + j2));
    float ex = __expf(mylg - mx);
    float sm = 0.f;
#pragma unroll
    for (int j2 = 0; j2 < 5; j2++) sm += __shfl_sync(FULL, ex, gbase + j2);
    float attl = __fdividef(ex, sm);

    if (att_out && lane < 25) att_out[(size_t)bn * 25 + lane] = attl;

    // broadcast attention weights to all lanes
    float attb[25];
#pragma unroll
    for (int e = 0; e < 25; e++) attb[e] = __shfl_sync(FULL, attl, e);

    // out[d=lane] = (1/5) * sum_h sum_k att[h,k]*kv[k][h,lane]
    float od = 0.f;
#pragma unroll
    for (int h = 0; h < 5; h++) {
        float s = 0.f;
#pragma unroll
        for (int k = 0; k < 5; k++) s = fmaf(attb[h * 5 + k], kvr[k][h], s);
        od += s;
    }
    od *= 0.2f;

    // proj(expmap0(out)) -> hnn_layer(W2, b2)
    float xr[1], xn2v[1];
    xr[0] = ball_point(od, xn2v[0]);
    float o2[1][1], no2[1];
    hnn_batch<1, 1>(sW2t, shb2, y2b, xr, xn2v, lane, o2, no2);
    out[(size_t)bn * 32 + lane] = o2[0][0];
}

// reset the gate for graph replay (runs after k_all in stream order)
__global__ void k_reset() { g_done = 0; }

// ---------------- launch ----------------
extern "C" void kernel_launch(void* const* d_in, const int* in_sizes, int n_in,
                              void* d_out, int out_size) {
    const float* in_feats = (const float*)d_in[0];
    const float* in_nei   = (const float*)d_in[1];
    const float* W1       = (const float*)d_in[2];
    const float* b1       = (const float*)d_in[3];
    const float* W2       = (const float*)d_in[4];
    const float* b2       = (const float*)d_in[5];
    float* out = (float*)d_out;
    // out (B*N*32 = 256000) followed by att_record (B*N*5*5 = 200000), if present.
    float* att = (out_size >= ROWS * 32 + ROWS * 25) ? (out + ROWS * 32) : nullptr;

    k_all<<<HNN1_BLOCKS + GATHER_BLOCKS, 256>>>(in_feats, in_nei, W1, b1, W2, b2, out, att);
    k_reset<<<1, 1>>>();
}